// round 14
// baseline (speedup 1.0000x reference)
#include <cuda_runtime.h>
#include <cuda_fp16.h>
#include <cstdint>

#define DM     1024
#define NH     16
#define DH     64
#define SEQ    2048
#define BATCH  2
#define M_TOT  (BATCH * SEQ)   // 4096

typedef unsigned long long ull;

// ---- fp16 scratch (all plain) ----
__device__ __half g_x16[(size_t)M_TOT * DM];
__device__ __half g_s16[(size_t)M_TOT * DM];
__device__ __half g_q16[(size_t)M_TOT * DM];          // Q (pre-scaled)
__device__ __half g_k16[(size_t)M_TOT * DM];
__device__ __half g_v16[(size_t)M_TOT * DM];
__device__ __half g_o16[(size_t)M_TOT * DM];
__device__ __half g_wq16[DM * DM];
__device__ __half g_wk16[DM * DM];
__device__ __half g_wv16[DM * DM];
__device__ __half g_wo16[DM * DM];

// ===========================================================================
// Helpers
// ===========================================================================
__device__ __forceinline__ uint32_t smem_u32(const void* p) {
    uint32_t a;
    asm("{ .reg .u64 t; cvta.to.shared.u64 t, %1; cvt.u32.u64 %0, t; }"
        : "=r"(a) : "l"(p));
    return a;
}
__device__ __forceinline__ void ldsm4(uint32_t* r, uint32_t addr) {
    asm volatile("ldmatrix.sync.aligned.m8n8.x4.shared.b16 {%0,%1,%2,%3}, [%4];"
                 : "=r"(r[0]), "=r"(r[1]), "=r"(r[2]), "=r"(r[3]) : "r"(addr));
}
__device__ __forceinline__ void ldsm4t(uint32_t* r, uint32_t addr) {
    asm volatile("ldmatrix.sync.aligned.m8n8.x4.trans.shared.b16 {%0,%1,%2,%3}, [%4];"
                 : "=r"(r[0]), "=r"(r[1]), "=r"(r[2]), "=r"(r[3]) : "r"(addr));
}
__device__ __forceinline__ void cpa16(uint32_t saddr, const void* gaddr) {
    asm volatile("cp.async.cg.shared.global [%0], [%1], 16;"
                 :: "r"(saddr), "l"(gaddr) : "memory");
}
#define CP_COMMIT asm volatile("cp.async.commit_group;" ::: "memory")
#define CP_WAIT0  asm volatile("cp.async.wait_group 0;" ::: "memory")
#define CP_WAIT1  asm volatile("cp.async.wait_group 1;" ::: "memory")

#define MMA_F16(d, a, b0, b1) \
    asm volatile("mma.sync.aligned.m16n8k16.row.col.f32.f16.f16.f32 " \
                 "{%0,%1,%2,%3},{%4,%5,%6,%7},{%8,%9},{%0,%1,%2,%3};" \
                 : "+f"((d)[0]), "+f"((d)[1]), "+f"((d)[2]), "+f"((d)[3]) \
                 : "r"((a)[0]), "r"((a)[1]), "r"((a)[2]), "r"((a)[3]), \
                   "r"(b0), "r"(b1))

__device__ __forceinline__ uint32_t pack_h2(float x, float y) {
    __half2 p = __floats2half2_rn(x, y);
    return *reinterpret_cast<uint32_t*>(&p);
}
__device__ __forceinline__ float fexp2(float x) {   // scalar (clamped) version
    x = fmaxf(x, -126.0f);
    float z = x + 12582912.0f;
    float f = x - (z - 12582912.0f);
    float p = 0.0013333558f;
    p = fmaf(p, f, 0.0096181291f);
    p = fmaf(p, f, 0.0555041087f);
    p = fmaf(p, f, 0.2402265069f);
    p = fmaf(p, f, 0.6931471806f);
    p = fmaf(p, f, 1.0f);
    return __uint_as_float(__float_as_uint(p) + (__float_as_uint(z) << 23));
}

// ---- packed f32x2 primitives (sm_103a FFMA2 path) ----
__device__ __forceinline__ ull pk2(float a, float b) {
    ull d;
    asm("mov.b64 %0, {%1, %2};" : "=l"(d)
        : "r"(__float_as_uint(a)), "r"(__float_as_uint(b)));
    return d;
}
__device__ __forceinline__ void upk2(ull d, uint32_t& a, uint32_t& b) {
    asm("mov.b64 {%0, %1}, %2;" : "=r"(a), "=r"(b) : "l"(d));
}
__device__ __forceinline__ ull add2(ull a, ull b) {
    ull d;
    asm("add.rn.f32x2 %0, %1, %2;" : "=l"(d) : "l"(a), "l"(b));
    return d;
}
__device__ __forceinline__ ull fma2(ull a, ull b, ull c) {
    ull d;
    asm("fma.rn.f32x2 %0, %1, %2, %3;" : "=l"(d) : "l"(a), "l"(b), "l"(c));
    return d;
}

// ===========================================================================
// Fused prep: all six fp32 -> plain fp16 conversions in ONE launch.
// ===========================================================================
#define N4X (M_TOT * DM / 4)      // 1048576
#define N4W (DM * DM / 4)         // 262144
#define N4TOT (2 * N4X + 4 * N4W) // 3145728

__global__ __launch_bounds__(256)
void prep_all(const float4* __restrict__ x,   const float4* __restrict__ src,
              const float4* __restrict__ Wq,  const float4* __restrict__ Wk,
              const float4* __restrict__ Wv,  const float4* __restrict__ Wo,
              uint2* __restrict__ x16,  uint2* __restrict__ s16,
              uint2* __restrict__ wq16, uint2* __restrict__ wk16,
              uint2* __restrict__ wv16, uint2* __restrict__ wo16,
              float qs) {
    int i = blockIdx.x * blockDim.x + threadIdx.x;
    if (i >= N4TOT) return;

    const float4* src_p;
    uint2* dst_p;
    int j;
    float scale = 1.f;
    if (i < N4X)                { src_p = x;  dst_p = x16;  j = i; }
    else if (i < 2 * N4X)       { src_p = src; dst_p = s16; j = i - N4X; }
    else {
        j = i - 2 * N4X;
        if (j < N4W)            { src_p = Wq; dst_p = wq16; scale = qs; }
        else if (j < 2 * N4W)   { src_p = Wk; dst_p = wk16; j -= N4W; }
        else if (j < 3 * N4W)   { src_p = Wv; dst_p = wv16; j -= 2 * N4W; }
        else                    { src_p = Wo; dst_p = wo16; j -= 3 * N4W; }
    }
    float4 v = src_p[j];
    v.x *= scale; v.y *= scale; v.z *= scale; v.w *= scale;
    dst_p[j] = make_uint2(pack_h2(v.x, v.y), pack_h2(v.z, v.w));
}

// ===========================================================================
// fp16 1-MMA GEMM core: 64x64 CTA tile, 128 threads (2x2 warps, 32x32 each),
// KC=32, 3-stage cp.async pipeline. High occupancy (~7 CTAs/SM).
// ===========================================================================
#define LDT2 80
#define TILE_A 5120                      // 64 rows x 80B
#define STG64  (2 * TILE_A)              // A + B = 10240
#define GSMEM  (3 * STG64)               // 30720

__device__ __forceinline__ void g_issue64(uint32_t ss, const char* A,
                                          const char* B, int m0, int n0,
                                          uint32_t k0b, int t) {
#pragma unroll
    for (int i = 0; i < 4; i++) {
        const char* g = (i < 2) ? A : B;
        const uint32_t slot = (i < 2) ? 0u : 1u;
        const int r0 = (i < 2) ? m0 : n0;
        const int idx = ((i & 1) << 7) + t;     // 0..255
        const int row = idx >> 2;               // 0..63
        const uint32_t c16 = (uint32_t)(idx & 3) << 4;
        cpa16(ss + slot * (uint32_t)TILE_A + (uint32_t)row * LDT2 + c16,
              g + (size_t)(r0 + row) * 2048 + k0b + c16);
    }
}

__device__ __forceinline__ void gemm_core64(const char* A, const char* B,
                                            uint32_t sbase, int m0, int n0,
                                            float (&acc)[2][4][4]) {
    const int t    = threadIdx.x;
    const int lane = t & 31;
    const int wid  = t >> 5;      // 0..3
    const int wm   = wid & 1;     // 2 in M
    const int wn   = wid >> 1;    // 2 in N

#pragma unroll
    for (int mi = 0; mi < 2; mi++)
#pragma unroll
        for (int ni = 0; ni < 4; ni++)
#pragma unroll
            for (int e = 0; e < 4; e++) acc[mi][ni][e] = 0.f;

    const int r8  = lane & 7;
    const int sel = lane >> 3;
    const uint32_t aRowOff = (uint32_t)(wm * 32 + (sel & 1) * 8 + r8) * LDT2
                           + (uint32_t)((sel >> 1) * 16);
    const uint32_t bRowOff = (uint32_t)(wn * 32 + (sel >> 1) * 8 + r8) * LDT2
                           + (uint32_t)((sel & 1) * 16);

    auto compute = [&](uint32_t sb) {
        const uint32_t sA = sb;
        const uint32_t sB = sb + TILE_A;
#pragma unroll
        for (int ks = 0; ks < 2; ks++) {
            const uint32_t kb = (uint32_t)ks * 32;
            uint32_t ah[2][4];
#pragma unroll
            for (int mi = 0; mi < 2; mi++)
                ldsm4(ah[mi], sA + aRowOff + (uint32_t)(mi * 16) * LDT2 + kb);
            uint32_t bh[2][4];
#pragma unroll
            for (int np = 0; np < 2; np++)
                ldsm4(bh[np], sB + bRowOff + (uint32_t)(np * 16) * LDT2 + kb);
#pragma unroll
            for (int mi = 0; mi < 2; mi++)
#pragma unroll
                for (int ni = 0; ni < 4; ni++)
                    MMA_F16(acc[mi][ni], ah[mi],
                            bh[ni >> 1][(ni & 1) * 2],
                            bh[ni >> 1][(ni & 1) * 2 + 1]);
        }
    };

    g_issue64(sbase,         A, B, m0, n0, 0u,  t);  CP_COMMIT;
    g_issue64(sbase + STG64, A, B, m0, n0, 64u, t);  CP_COMMIT;

    const int NCHUNK = DM / 32;   // 32
    uint32_t soff[3] = {0u, (uint32_t)STG64, (uint32_t)(2 * STG64)};
    int s = 0;
    for (int chunk = 0; chunk < NCHUNK; chunk++) {
        if (chunk + 1 < NCHUNK) { CP_WAIT1; } else { CP_WAIT0; }
        __syncthreads();
        if (chunk + 2 < NCHUNK) {
            int s2 = s + 2; if (s2 >= 3) s2 -= 3;
            g_issue64(sbase + soff[s2], A, B, m0, n0,
                      (uint32_t)(chunk + 2) * 64, t);
            CP_COMMIT;
        }
        compute(sbase + soff[s]);
        if (++s == 3) s = 0;
    }
}

// QKV projections: z selects (A, B, Y). Plain fp16 out.
__global__ __launch_bounds__(128)
void gemm_qkv7(const char* x16, const char* s16,
               const char* wq16, const char* wk16, const char* wv16,
               uint32_t* q16, uint32_t* k16, uint32_t* v16) {
    extern __shared__ __align__(16) char sm[];
    const int z  = blockIdx.z;
    const int m0 = blockIdx.y * 64;
    const int n0 = blockIdx.x * 64;
    const char* A = (z == 0) ? x16 : s16;
    const char* B = (z == 0) ? wq16 : (z == 1 ? wk16 : wv16);
    uint32_t* Y   = (z == 0) ? q16 : (z == 1 ? k16 : v16);

    float acc[2][4][4];
    gemm_core64(A, B, smem_u32(sm), m0, n0, acc);

    const int lane = threadIdx.x & 31;
    const int wid  = threadIdx.x >> 5;
    const int wm   = wid & 1, wn = wid >> 1;
    const int g  = lane >> 2;
    const int c2 = (lane & 3) * 2;
#pragma unroll
    for (int mi = 0; mi < 2; mi++) {
#pragma unroll
        for (int ni = 0; ni < 4; ni++) {
            int row = m0 + wm * 32 + mi * 16 + g;
            int col = n0 + wn * 32 + ni * 8 + c2;
            Y[((size_t)row * DM + col) >> 1]       = pack_h2(acc[mi][ni][0], acc[mi][ni][1]);
            Y[((size_t)(row + 8) * DM + col) >> 1] = pack_h2(acc[mi][ni][2], acc[mi][ni][3]);
        }
    }
}

// Output projection: fp32 epilogue.
__global__ __launch_bounds__(128)
void gemm_out7(const char* o16, const char* wo16, float* __restrict__ Y) {
    extern __shared__ __align__(16) char sm[];
    const int m0 = blockIdx.y * 64;
    const int n0 = blockIdx.x * 64;

    float acc[2][4][4];
    gemm_core64(o16, wo16, smem_u32(sm), m0, n0, acc);

    const int lane = threadIdx.x & 31;
    const int wid  = threadIdx.x >> 5;
    const int wm   = wid & 1, wn = wid >> 1;
    const int g  = lane >> 2;
    const int c2 = (lane & 3) * 2;
#pragma unroll
    for (int mi = 0; mi < 2; mi++) {
#pragma unroll
        for (int ni = 0; ni < 4; ni++) {
            int row = m0 + wm * 32 + mi * 16 + g;
            int col = n0 + wn * 32 + ni * 8 + c2;
            float2 v0 = {acc[mi][ni][0], acc[mi][ni][1]};
            float2 v1 = {acc[mi][ni][2], acc[mi][ni][3]};
            *(float2*)(Y + (size_t)row * DM + col)       = v0;
            *(float2*)(Y + (size_t)(row + 8) * DM + col) = v1;
        }
    }
}

// ===========================================================================
// Flash attention v10: same structure as v9, softmax exp2 via packed f32x2
// (bit-identical per-lane RN arithmetic; args bounded so no clamp needed).
// ===========================================================================
#define QROW_B 144
#define FT     9216
#define FQ     0
#define FK(s)  ((uint32_t)(1 + (s)) * FT)
#define FV(s)  ((uint32_t)(3 + (s)) * FT)
#define FSMEM  (5 * FT)                  // 46080

__global__ __launch_bounds__(128, 4)
void flash_v10(const char* Q16, const char* K16, const char* V16,
               uint32_t* O16) {
    extern __shared__ __align__(16) char fsm[];
    const uint32_t sb = smem_u32(fsm);

    const int t    = threadIdx.x;
    const int lane = t & 31;
    const int wid  = t >> 5;
    const int b    = blockIdx.z;
    const int h    = blockIdx.y;
    const int q0   = blockIdx.x * 64;
    const size_t rq  = (size_t)(b * SEQ + q0);
    const size_t rb0 = (size_t)(b * SEQ);
    const uint32_t hoff = (uint32_t)h * 128u;

    const int rI  = t >> 3;
    const uint32_t c16 = (uint32_t)(t & 7) << 4;

    auto load_kv = [&](int kt, int s) {
        const size_t r0 = rb0 + (size_t)kt * 64;
#pragma unroll
        for (int i = 0; i < 4; i++) {
            const int row = (i << 4) + rI;
            cpa16(sb + FK(s) + (uint32_t)row * QROW_B + c16,
                  K16 + (r0 + row) * 2048 + hoff + c16);
        }
#pragma unroll
        for (int i = 0; i < 4; i++) {
            const int row = (i << 4) + rI;
            cpa16(sb + FV(s) + (uint32_t)row * QROW_B + c16,
                  V16 + (r0 + row) * 2048 + hoff + c16);
        }
    };

#pragma unroll
    for (int i = 0; i < 4; i++) {
        const int row = (i << 4) + rI;
        cpa16(sb + FQ + (uint32_t)row * QROW_B + c16,
              Q16 + (rq + row) * 2048 + hoff + c16);
    }
    load_kv(0, 0);
    CP_COMMIT;

    const int r8  = lane & 7;
    const int sel = lane >> 3;
    const uint32_t aOff = (uint32_t)(wid * 16 + (sel & 1) * 8 + r8) * QROW_B
                        + (uint32_t)((sel >> 1) * 16);
    const uint32_t bOff = (uint32_t)((sel >> 1) * 8 + r8) * QROW_B
                        + (uint32_t)((sel & 1) * 16);
    const uint32_t vOff = (uint32_t)((sel & 1) * 8 + r8) * QROW_B
                        + (uint32_t)((sel >> 1) * 16);

    // packed exp2 constants (loop invariant)
    const ull C2  = pk2(12582912.0f, 12582912.0f);
    const ull NC2 = pk2(-12582912.0f, -12582912.0f);
    const ull N12 = pk2(-1.0f, -1.0f);
    const ull KA2 = pk2(0.0013333558f, 0.0013333558f);
    const ull KB2 = pk2(0.0096181291f, 0.0096181291f);
    const ull KC2 = pk2(0.0555041087f, 0.0555041087f);
    const ull KD2 = pk2(0.2402265069f, 0.2402265069f);
    const ull KE2 = pk2(0.6931471806f, 0.6931471806f);
    const ull ON2 = pk2(1.0f, 1.0f);

    float m_s[2] = {-1.0e30f, -1.0e30f};
    float l_s[2] = {0.f, 0.f};
    float o[8][4];
#pragma unroll
    for (int j = 0; j < 8; j++)
#pragma unroll
        for (int e = 0; e < 4; e++) o[j][e] = 0.f;

    const int NT = SEQ / 64;
    for (int kt = 0; kt < NT; kt++) {
        const int s = kt & 1;

        CP_WAIT0;
        __syncthreads();

        if (kt + 1 < NT) {
            load_kv(kt + 1, s ^ 1);
            CP_COMMIT;
        }

        // ---- S = Q @ K^T (1-MMA) ----
        float sc[8][4];
#pragma unroll
        for (int j = 0; j < 8; j++)
#pragma unroll
            for (int e = 0; e < 4; e++) sc[j][e] = 0.f;

#pragma unroll
        for (int kc = 0; kc < 4; kc++) {
            const uint32_t kb = (uint32_t)kc * 32;
            uint32_t aq[4];
            ldsm4(aq, sb + FQ + aOff + kb);
#pragma unroll
            for (int j = 0; j < 4; j++) {
                uint32_t bk[4];
                ldsm4(bk, sb + FK(s) + bOff + (uint32_t)(j * 16) * QROW_B + kb);
                MMA_F16(sc[2 * j],     aq, bk[0], bk[1]);
                MMA_F16(sc[2 * j + 1], aq, bk[2], bk[3]);
            }
        }

        // ---- online softmax (log2 domain, packed f32x2 exp) ----
        float mx0 = sc[0][0], mx1 = sc[0][2];
#pragma unroll
        for (int j = 0; j < 8; j++) {
            mx0 = fmaxf(mx0, fmaxf(sc[j][0], sc[j][1]));
            mx1 = fmaxf(mx1, fmaxf(sc[j][2], sc[j][3]));
        }
        mx0 = fmaxf(mx0, __shfl_xor_sync(0xffffffffu, mx0, 1));
        mx0 = fmaxf(mx0, __shfl_xor_sync(0xffffffffu, mx0, 2));
        mx1 = fmaxf(mx1, __shfl_xor_sync(0xffffffffu, mx1, 1));
        mx1 = fmaxf(mx1, __shfl_xor_sync(0xffffffffu, mx1, 2));

        const float mn0 = fmaxf(m_s[0], mx0);
        const float mn1 = fmaxf(m_s[1], mx1);
        const float al0 = fexp2(m_s[0] - mn0);   // scalar: arg may be -huge
        const float al1 = fexp2(m_s[1] - mn1);
        m_s[0] = mn0; m_s[1] = mn1;

        const ull nm0 = pk2(-mn0, -mn0);
        const ull nm1 = pk2(-mn1, -mn1);

        float sum0 = 0.f, sum1 = 0.f;
#pragma unroll
        for (int j = 0; j < 8; j++) {
            // pair (row g): sc[j][0], sc[j][1];  pair (row g+8): sc[j][2], sc[j][3]
#pragma unroll
            for (int pidx = 0; pidx < 2; pidx++) {
                ull s2 = pk2(sc[j][2 * pidx], sc[j][2 * pidx + 1]);
                ull xv = add2(s2, pidx ? nm1 : nm0);   // x = s - mn  (in [-~100, 0])
                ull zv = add2(xv, C2);                 // magic round
                ull wv = add2(zv, NC2);                // round(x), exact
                ull fv = fma2(wv, N12, xv);            // f = x - round(x), exact
                ull pv = fma2(KA2, fv, KB2);
                pv = fma2(pv, fv, KC2);
                pv = fma2(pv, fv, KD2);
                pv = fma2(pv, fv, KE2);
                pv = fma2(pv, fv, ON2);
                uint32_t zu0, zu1, pu0, pu1;
                upk2(zv, zu0, zu1);
                upk2(pv, pu0, pu1);
                sc[j][2 * pidx]     = __uint_as_float(pu0 + (zu0 << 23));
                sc[j][2 * pidx + 1] = __uint_as_float(pu1 + (zu1 << 23));
            }
            sum0 += sc[j][0] + sc[j][1];
            sum1 += sc[j][2] + sc[j][3];
        }
        sum0 += __shfl_xor_sync(0xffffffffu, sum0, 1);
        sum0 += __shfl_xor_sync(0xffffffffu, sum0, 2);
        sum1 += __shfl_xor_sync(0xffffffffu, sum1, 1);
        sum1 += __shfl_xor_sync(0xffffffffu, sum1, 2);
        l_s[0] = l_s[0] * al0 + sum0;
        l_s[1] = l_s[1] * al1 + sum1;

#pragma unroll
        for (int j = 0; j < 8; j++) {
            o[j][0] *= al0; o[j][1] *= al0;
            o[j][2] *= al1; o[j][3] *= al1;
        }

        // ---- PV (1-MMA) ----
#pragma unroll
        for (int kk = 0; kk < 4; kk++) {
            float* s0 = sc[2 * kk];
            float* s1 = sc[2 * kk + 1];
            uint32_t pa[4];
            pa[0] = pack_h2(s0[0], s0[1]);
            pa[1] = pack_h2(s0[2], s0[3]);
            pa[2] = pack_h2(s1[0], s1[1]);
            pa[3] = pack_h2(s1[2], s1[3]);
            const uint32_t rowk = (uint32_t)(kk * 16) * QROW_B;
#pragma unroll
            for (int j = 0; j < 4; j++) {
                uint32_t vv[4];
                ldsm4t(vv, sb + FV(s) + vOff + rowk + (uint32_t)(j * 32));
                MMA_F16(o[2 * j],     pa, vv[0], vv[1]);
                MMA_F16(o[2 * j + 1], pa, vv[2], vv[3]);
            }
        }
    }

    // ---- epilogue: O plain fp16 ----
    const int g  = lane >> 2;
    const int c2 = (lane & 3) * 2;
    const float inv0 = 1.f / l_s[0];
    const float inv1 = 1.f / l_s[1];
    const size_t row0 = rq + (size_t)(wid * 16 + g);
#pragma unroll
    for (int j = 0; j < 8; j++) {
        size_t i0 = (row0 * DM + h * DH + j * 8 + c2) >> 1;
        size_t i1 = ((row0 + 8) * DM + h * DH + j * 8 + c2) >> 1;
        O16[i0] = pack_h2(o[j][0] * inv0, o[j][1] * inv0);
        O16[i1] = pack_h2(o[j][2] * inv1, o[j][3] * inv1);
    }
}

// ---------------------------------------------------------------------------
// Launch
// ---------------------------------------------------------------------------
extern "C" void kernel_launch(void* const* d_in, const int* in_sizes, int n_in,
                              void* d_out, int out_size) {
    const float* x   = (const float*)d_in[0];
    const float* src = (const float*)d_in[1];
    const float* Wq  = (const float*)d_in[2];
    const float* Wk  = (const float*)d_in[3];
    const float* Wv  = (const float*)d_in[4];
    const float* Wo  = (const float*)d_in[5];
    float* out = (float*)d_out;

    void *x16, *s16, *q16, *k16, *v16, *o16;
    void *wq16, *wk16, *wv16, *wo16;
    cudaGetSymbolAddress(&x16, g_x16);
    cudaGetSymbolAddress(&s16, g_s16);
    cudaGetSymbolAddress(&q16, g_q16);
    cudaGetSymbolAddress(&k16, g_k16);
    cudaGetSymbolAddress(&v16, g_v16);
    cudaGetSymbolAddress(&o16, g_o16);
    cudaGetSymbolAddress(&wq16, g_wq16);
    cudaGetSymbolAddress(&wk16, g_wk16);
    cudaGetSymbolAddress(&wv16, g_wv16);
    cudaGetSymbolAddress(&wo16, g_wo16);

    cudaFuncSetAttribute(gemm_qkv7, cudaFuncAttributeMaxDynamicSharedMemorySize, GSMEM);
    cudaFuncSetAttribute(gemm_out7, cudaFuncAttributeMaxDynamicSharedMemorySize, GSMEM);
    cudaFuncSetAttribute(flash_v10, cudaFuncAttributeMaxDynamicSharedMemorySize, FSMEM);

    const float qs = 0.125f * 1.4426950408889634f;

    prep_all<<<(N4TOT + 255) / 256, 256>>>(
        (const float4*)x, (const float4*)src, (const float4*)Wq,
        (const float4*)Wk, (const float4*)Wv, (const float4*)Wo,
        (uint2*)x16, (uint2*)s16, (uint2*)wq16, (uint2*)wk16,
        (uint2*)wv16, (uint2*)wo16, qs);

    dim3 qkvgrid(DM / 64, M_TOT / 64, 3);      // (16, 64, 3)
    gemm_qkv7<<<qkvgrid, 128, GSMEM>>>(
        (const char*)x16, (const char*)s16,
        (const char*)wq16, (const char*)wk16, (const char*)wv16,
        (uint32_t*)q16, (uint32_t*)k16, (uint32_t*)v16);

    dim3 agrid(SEQ / 64, NH, BATCH);           // (32, 16, 2)
    flash_v10<<<agrid, 128, FSMEM>>>(
        (const char*)q16, (const char*)k16, (const char*)v16, (uint32_t*)o16);

    dim3 ggrid(DM / 64, M_TOT / 64);           // (16, 64)
    gemm_out7<<<ggrid, 128, GSMEM>>>(
        (const char*)o16, (const char*)wo16, out);
}

// round 15
// speedup vs baseline: 1.0810x; 1.0810x over previous
#include <cuda_runtime.h>
#include <cuda_fp16.h>
#include <cstdint>

#define DM     1024
#define NH     16
#define DH     64
#define SEQ    2048
#define BATCH  2
#define M_TOT  (BATCH * SEQ)   // 4096

typedef unsigned long long ull;

// ---- fp16 scratch (all plain) ----
__device__ __half g_x16[(size_t)M_TOT * DM];
__device__ __half g_s16[(size_t)M_TOT * DM];
__device__ __half g_q16[(size_t)M_TOT * DM];          // Q (pre-scaled)
__device__ __half g_k16[(size_t)M_TOT * DM];
__device__ __half g_v16[(size_t)M_TOT * DM];
__device__ __half g_o16[(size_t)M_TOT * DM];
__device__ __half g_wq16[DM * DM];
__device__ __half g_wk16[DM * DM];
__device__ __half g_wv16[DM * DM];
__device__ __half g_wo16[DM * DM];

// ===========================================================================
// Helpers
// ===========================================================================
__device__ __forceinline__ uint32_t smem_u32(const void* p) {
    uint32_t a;
    asm("{ .reg .u64 t; cvta.to.shared.u64 t, %1; cvt.u32.u64 %0, t; }"
        : "=r"(a) : "l"(p));
    return a;
}
__device__ __forceinline__ void ldsm4(uint32_t* r, uint32_t addr) {
    asm volatile("ldmatrix.sync.aligned.m8n8.x4.shared.b16 {%0,%1,%2,%3}, [%4];"
                 : "=r"(r[0]), "=r"(r[1]), "=r"(r[2]), "=r"(r[3]) : "r"(addr));
}
__device__ __forceinline__ void ldsm4t(uint32_t* r, uint32_t addr) {
    asm volatile("ldmatrix.sync.aligned.m8n8.x4.trans.shared.b16 {%0,%1,%2,%3}, [%4];"
                 : "=r"(r[0]), "=r"(r[1]), "=r"(r[2]), "=r"(r[3]) : "r"(addr));
}
__device__ __forceinline__ void cpa16(uint32_t saddr, const void* gaddr) {
    asm volatile("cp.async.cg.shared.global [%0], [%1], 16;"
                 :: "r"(saddr), "l"(gaddr) : "memory");
}
#define CP_COMMIT asm volatile("cp.async.commit_group;" ::: "memory")
#define CP_WAIT0  asm volatile("cp.async.wait_group 0;" ::: "memory")

#define MMA_F16(d, a, b0, b1) \
    asm volatile("mma.sync.aligned.m16n8k16.row.col.f32.f16.f16.f32 " \
                 "{%0,%1,%2,%3},{%4,%5,%6,%7},{%8,%9},{%0,%1,%2,%3};" \
                 : "+f"((d)[0]), "+f"((d)[1]), "+f"((d)[2]), "+f"((d)[3]) \
                 : "r"((a)[0]), "r"((a)[1]), "r"((a)[2]), "r"((a)[3]), \
                   "r"(b0), "r"(b1))

__device__ __forceinline__ uint32_t pack_h2(float x, float y) {
    __half2 p = __floats2half2_rn(x, y);
    return *reinterpret_cast<uint32_t*>(&p);
}
__device__ __forceinline__ float fexp2(float x) {   // scalar (clamped)
    x = fmaxf(x, -126.0f);
    float z = x + 12582912.0f;
    float f = x - (z - 12582912.0f);
    float p = 0.0013333558f;
    p = fmaf(p, f, 0.0096181291f);
    p = fmaf(p, f, 0.0555041087f);
    p = fmaf(p, f, 0.2402265069f);
    p = fmaf(p, f, 0.6931471806f);
    p = fmaf(p, f, 1.0f);
    return __uint_as_float(__float_as_uint(p) + (__float_as_uint(z) << 23));
}

// ---- packed f32x2 primitives ----
__device__ __forceinline__ ull pk2(float a, float b) {
    ull d;
    asm("mov.b64 %0, {%1, %2};" : "=l"(d)
        : "r"(__float_as_uint(a)), "r"(__float_as_uint(b)));
    return d;
}
__device__ __forceinline__ void upk2(ull d, uint32_t& a, uint32_t& b) {
    asm("mov.b64 {%0, %1}, %2;" : "=r"(a), "=r"(b) : "l"(d));
}
__device__ __forceinline__ ull add2(ull a, ull b) {
    ull d;
    asm("add.rn.f32x2 %0, %1, %2;" : "=l"(d) : "l"(a), "l"(b));
    return d;
}
__device__ __forceinline__ ull fma2(ull a, ull b, ull c) {
    ull d;
    asm("fma.rn.f32x2 %0, %1, %2, %3;" : "=l"(d) : "l"(a), "l"(b), "l"(c));
    return d;
}

// ===========================================================================
// Fused prep: all six fp32 -> plain fp16 conversions in ONE launch.
// ===========================================================================
#define N4X (M_TOT * DM / 4)      // 1048576
#define N4W (DM * DM / 4)         // 262144
#define N4TOT (2 * N4X + 4 * N4W) // 3145728

__global__ __launch_bounds__(256)
void prep_all(const float4* __restrict__ x,   const float4* __restrict__ src,
              const float4* __restrict__ Wq,  const float4* __restrict__ Wk,
              const float4* __restrict__ Wv,  const float4* __restrict__ Wo,
              uint2* __restrict__ x16,  uint2* __restrict__ s16,
              uint2* __restrict__ wq16, uint2* __restrict__ wk16,
              uint2* __restrict__ wv16, uint2* __restrict__ wo16,
              float qs) {
    int i = blockIdx.x * blockDim.x + threadIdx.x;
    if (i >= N4TOT) return;

    const float4* src_p;
    uint2* dst_p;
    int j;
    float scale = 1.f;
    if (i < N4X)                { src_p = x;  dst_p = x16;  j = i; }
    else if (i < 2 * N4X)       { src_p = src; dst_p = s16; j = i - N4X; }
    else {
        j = i - 2 * N4X;
        if (j < N4W)            { src_p = Wq; dst_p = wq16; scale = qs; }
        else if (j < 2 * N4W)   { src_p = Wk; dst_p = wk16; j -= N4W; }
        else if (j < 3 * N4W)   { src_p = Wv; dst_p = wv16; j -= 2 * N4W; }
        else                    { src_p = Wo; dst_p = wo16; j -= 3 * N4W; }
    }
    float4 v = src_p[j];
    v.x *= scale; v.y *= scale; v.z *= scale; v.w *= scale;
    dst_p[j] = make_uint2(pack_h2(v.x, v.y), pack_h2(v.z, v.w));
}

// ===========================================================================
// fp16 1-MMA GEMM core (R12-proven config): Y = A @ B^T, 128x128 CTA tile,
// 256 threads, KC=32, TWO-stage cp.async pipeline.
// ===========================================================================
#define LDT2 80
#define TILE_BYTES (128 * LDT2)          // 10240
#define STG1 (2 * TILE_BYTES)            // A, B = 20480
#define GSMEM (2 * STG1)                 // 40960

__device__ __forceinline__ void g_issue1(uint32_t ss, const char* A,
                                         const char* B, int m0, int n0,
                                         uint32_t k0b, int t) {
#pragma unroll
    for (int i = 0; i < 4; i++) {
        const char* g = (i < 2) ? A : B;
        const uint32_t slot = (uint32_t)(i >> 1);
        const int r0 = (i < 2) ? m0 : n0;
        const int row = ((i & 1) << 6) + (t >> 2);
        const uint32_t c16 = (uint32_t)(t & 3) << 4;
        cpa16(ss + slot * (uint32_t)TILE_BYTES + (uint32_t)row * LDT2 + c16,
              g + (size_t)(r0 + row) * 2048 + k0b + c16);
    }
}

__device__ __forceinline__ void gemm_core1(const char* A, const char* B,
                                           uint32_t sbase, int m0, int n0,
                                           float (&acc)[4][4][4]) {
    const int t    = threadIdx.x;
    const int lane = t & 31;
    const int wid  = t >> 5;
    const int wm   = wid & 1;
    const int wn   = wid >> 1;

#pragma unroll
    for (int mi = 0; mi < 4; mi++)
#pragma unroll
        for (int ni = 0; ni < 4; ni++)
#pragma unroll
            for (int e = 0; e < 4; e++) acc[mi][ni][e] = 0.f;

    const int r8  = lane & 7;
    const int sel = lane >> 3;
    const uint32_t aRowOff = (uint32_t)(wm * 64 + (sel & 1) * 8 + r8) * LDT2
                           + (uint32_t)((sel >> 1) * 8) * 2;
    const uint32_t bRowOff = (uint32_t)(wn * 32 + (sel >> 1) * 8 + r8) * LDT2
                           + (uint32_t)((sel & 1) * 8) * 2;

    auto compute = [&](uint32_t sb) {
        const uint32_t sA = sb;
        const uint32_t sB = sb + TILE_BYTES;
#pragma unroll
        for (int ks = 0; ks < 2; ks++) {
            const uint32_t kb = (uint32_t)ks * 32;
            uint32_t ah[4][4];
#pragma unroll
            for (int mi = 0; mi < 4; mi++)
                ldsm4(ah[mi], sA + aRowOff + (uint32_t)(mi * 16) * LDT2 + kb);
            uint32_t bh[2][4];
#pragma unroll
            for (int np = 0; np < 2; np++)
                ldsm4(bh[np], sB + bRowOff + (uint32_t)(np * 16) * LDT2 + kb);
#pragma unroll
            for (int mi = 0; mi < 4; mi++)
#pragma unroll
                for (int ni = 0; ni < 4; ni++)
                    MMA_F16(acc[mi][ni], ah[mi],
                            bh[ni >> 1][(ni & 1) * 2],
                            bh[ni >> 1][(ni & 1) * 2 + 1]);
        }
    };

    g_issue1(sbase, A, B, m0, n0, 0u, t);
    CP_COMMIT;

    const int NCHUNK = DM / 32;   // 32
    for (int chunk = 0; chunk < NCHUNK; chunk++) {
        const int s = chunk & 1;
        CP_WAIT0;
        __syncthreads();
        if (chunk + 1 < NCHUNK) {
            g_issue1(sbase + (uint32_t)(s ^ 1) * STG1,
                     A, B, m0, n0, (uint32_t)(chunk + 1) * 64, t);
            CP_COMMIT;
        }
        compute(sbase + (uint32_t)s * STG1);
    }
}

// QKV projections: uniform 1-MMA, z selects (A, B, Y). Plain fp16 out.
__global__ __launch_bounds__(256, 2)
void gemm_qkv8(const char* x16, const char* s16,
               const char* wq16, const char* wk16, const char* wv16,
               uint32_t* q16, uint32_t* k16, uint32_t* v16) {
    extern __shared__ __align__(16) char sm[];
    const int z  = blockIdx.z;
    const int m0 = blockIdx.y * 128;
    const int n0 = blockIdx.x * 128;
    const char* A = (z == 0) ? x16 : s16;
    const char* B = (z == 0) ? wq16 : (z == 1 ? wk16 : wv16);
    uint32_t* Y   = (z == 0) ? q16 : (z == 1 ? k16 : v16);

    float acc[4][4][4];
    gemm_core1(A, B, smem_u32(sm), m0, n0, acc);

    const int lane = threadIdx.x & 31;
    const int wid  = threadIdx.x >> 5;
    const int wm   = wid & 1, wn = wid >> 1;
    const int g  = lane >> 2;
    const int c2 = (lane & 3) * 2;
#pragma unroll
    for (int mi = 0; mi < 4; mi++) {
#pragma unroll
        for (int ni = 0; ni < 4; ni++) {
            int row = m0 + wm * 64 + mi * 16 + g;
            int col = n0 + wn * 32 + ni * 8 + c2;
            Y[((size_t)row * DM + col) >> 1]       = pack_h2(acc[mi][ni][0], acc[mi][ni][1]);
            Y[((size_t)(row + 8) * DM + col) >> 1] = pack_h2(acc[mi][ni][2], acc[mi][ni][3]);
        }
    }
}

// Output projection: 1-MMA, fp32 epilogue.
__global__ __launch_bounds__(256, 2)
void gemm_out8(const char* o16, const char* wo16, float* __restrict__ Y) {
    extern __shared__ __align__(16) char sm[];
    const int m0 = blockIdx.y * 128;
    const int n0 = blockIdx.x * 128;

    float acc[4][4][4];
    gemm_core1(o16, wo16, smem_u32(sm), m0, n0, acc);

    const int lane = threadIdx.x & 31;
    const int wid  = threadIdx.x >> 5;
    const int wm   = wid & 1, wn = wid >> 1;
    const int g  = lane >> 2;
    const int c2 = (lane & 3) * 2;
#pragma unroll
    for (int mi = 0; mi < 4; mi++) {
#pragma unroll
        for (int ni = 0; ni < 4; ni++) {
            int row = m0 + wm * 64 + mi * 16 + g;
            int col = n0 + wn * 32 + ni * 8 + c2;
            float2 v0 = {acc[mi][ni][0], acc[mi][ni][1]};
            float2 v1 = {acc[mi][ni][2], acc[mi][ni][3]};
            *(float2*)(Y + (size_t)row * DM + col)       = v0;
            *(float2*)(Y + (size_t)(row + 8) * DM + col) = v1;
        }
    }
}

// ===========================================================================
// Flash attention v10 (unchanged from R14): QK 1-MMA, PV 1-MMA,
// K/V double-buffered, packed f32x2 exp2. 4 CTAs/SM.
// ===========================================================================
#define QROW_B 144
#define FT     9216
#define FQ     0
#define FK(s)  ((uint32_t)(1 + (s)) * FT)
#define FV(s)  ((uint32_t)(3 + (s)) * FT)
#define FSMEM  (5 * FT)                  // 46080

__global__ __launch_bounds__(128, 4)
void flash_v10(const char* Q16, const char* K16, const char* V16,
               uint32_t* O16) {
    extern __shared__ __align__(16) char fsm[];
    const uint32_t sb = smem_u32(fsm);

    const int t    = threadIdx.x;
    const int lane = t & 31;
    const int wid  = t >> 5;
    const int b    = blockIdx.z;
    const int h    = blockIdx.y;
    const int q0   = blockIdx.x * 64;
    const size_t rq  = (size_t)(b * SEQ + q0);
    const size_t rb0 = (size_t)(b * SEQ);
    const uint32_t hoff = (uint32_t)h * 128u;

    const int rI  = t >> 3;
    const uint32_t c16 = (uint32_t)(t & 7) << 4;

    auto load_kv = [&](int kt, int s) {
        const size_t r0 = rb0 + (size_t)kt * 64;
#pragma unroll
        for (int i = 0; i < 4; i++) {
            const int row = (i << 4) + rI;
            cpa16(sb + FK(s) + (uint32_t)row * QROW_B + c16,
                  K16 + (r0 + row) * 2048 + hoff + c16);
        }
#pragma unroll
        for (int i = 0; i < 4; i++) {
            const int row = (i << 4) + rI;
            cpa16(sb + FV(s) + (uint32_t)row * QROW_B + c16,
                  V16 + (r0 + row) * 2048 + hoff + c16);
        }
    };

#pragma unroll
    for (int i = 0; i < 4; i++) {
        const int row = (i << 4) + rI;
        cpa16(sb + FQ + (uint32_t)row * QROW_B + c16,
              Q16 + (rq + row) * 2048 + hoff + c16);
    }
    load_kv(0, 0);
    CP_COMMIT;

    const int r8  = lane & 7;
    const int sel = lane >> 3;
    const uint32_t aOff = (uint32_t)(wid * 16 + (sel & 1) * 8 + r8) * QROW_B
                        + (uint32_t)((sel >> 1) * 16);
    const uint32_t bOff = (uint32_t)((sel >> 1) * 8 + r8) * QROW_B
                        + (uint32_t)((sel & 1) * 16);
    const uint32_t vOff = (uint32_t)((sel & 1) * 8 + r8) * QROW_B
                        + (uint32_t)((sel >> 1) * 16);

    const ull C2  = pk2(12582912.0f, 12582912.0f);
    const ull NC2 = pk2(-12582912.0f, -12582912.0f);
    const ull N12 = pk2(-1.0f, -1.0f);
    const ull KA2 = pk2(0.0013333558f, 0.0013333558f);
    const ull KB2 = pk2(0.0096181291f, 0.0096181291f);
    const ull KC2 = pk2(0.0555041087f, 0.0555041087f);
    const ull KD2 = pk2(0.2402265069f, 0.2402265069f);
    const ull KE2 = pk2(0.6931471806f, 0.6931471806f);
    const ull ON2 = pk2(1.0f, 1.0f);

    float m_s[2] = {-1.0e30f, -1.0e30f};
    float l_s[2] = {0.f, 0.f};
    float o[8][4];
#pragma unroll
    for (int j = 0; j < 8; j++)
#pragma unroll
        for (int e = 0; e < 4; e++) o[j][e] = 0.f;

    const int NT = SEQ / 64;
    for (int kt = 0; kt < NT; kt++) {
        const int s = kt & 1;

        CP_WAIT0;
        __syncthreads();

        if (kt + 1 < NT) {
            load_kv(kt + 1, s ^ 1);
            CP_COMMIT;
        }

        float sc[8][4];
#pragma unroll
        for (int j = 0; j < 8; j++)
#pragma unroll
            for (int e = 0; e < 4; e++) sc[j][e] = 0.f;

#pragma unroll
        for (int kc = 0; kc < 4; kc++) {
            const uint32_t kb = (uint32_t)kc * 32;
            uint32_t aq[4];
            ldsm4(aq, sb + FQ + aOff + kb);
#pragma unroll
            for (int j = 0; j < 4; j++) {
                uint32_t bk[4];
                ldsm4(bk, sb + FK(s) + bOff + (uint32_t)(j * 16) * QROW_B + kb);
                MMA_F16(sc[2 * j],     aq, bk[0], bk[1]);
                MMA_F16(sc[2 * j + 1], aq, bk[2], bk[3]);
            }
        }

        float mx0 = sc[0][0], mx1 = sc[0][2];
#pragma unroll
        for (int j = 0; j < 8; j++) {
            mx0 = fmaxf(mx0, fmaxf(sc[j][0], sc[j][1]));
            mx1 = fmaxf(mx1, fmaxf(sc[j][2], sc[j][3]));
        }
        mx0 = fmaxf(mx0, __shfl_xor_sync(0xffffffffu, mx0, 1));
        mx0 = fmaxf(mx0, __shfl_xor_sync(0xffffffffu, mx0, 2));
        mx1 = fmaxf(mx1, __shfl_xor_sync(0xffffffffu, mx1, 1));
        mx1 = fmaxf(mx1, __shfl_xor_sync(0xffffffffu, mx1, 2));

        const float mn0 = fmaxf(m_s[0], mx0);
        const float mn1 = fmaxf(m_s[1], mx1);
        const float al0 = fexp2(m_s[0] - mn0);
        const float al1 = fexp2(m_s[1] - mn1);
        m_s[0] = mn0; m_s[1] = mn1;

        const ull nm0 = pk2(-mn0, -mn0);
        const ull nm1 = pk2(-mn1, -mn1);

        float sum0 = 0.f, sum1 = 0.f;
#pragma unroll
        for (int j = 0; j < 8; j++) {
#pragma unroll
            for (int pidx = 0; pidx < 2; pidx++) {
                ull s2 = pk2(sc[j][2 * pidx], sc[j][2 * pidx + 1]);
                ull xv = add2(s2, pidx ? nm1 : nm0);
                ull zv = add2(xv, C2);
                ull wv = add2(zv, NC2);
                ull fv = fma2(wv, N12, xv);
                ull pv = fma2(KA2, fv, KB2);
                pv = fma2(pv, fv, KC2);
                pv = fma2(pv, fv, KD2);
                pv = fma2(pv, fv, KE2);
                pv = fma2(pv, fv, ON2);
                uint32_t zu0, zu1, pu0, pu1;
                upk2(zv, zu0, zu1);
                upk2(pv, pu0, pu1);
                sc[j][2 * pidx]     = __uint_as_float(pu0 + (zu0 << 23));
                sc[j][2 * pidx + 1] = __uint_as_float(pu1 + (zu1 << 23));
            }
            sum0 += sc[j][0] + sc[j][1];
            sum1 += sc[j][2] + sc[j][3];
        }
        sum0 += __shfl_xor_sync(0xffffffffu, sum0, 1);
        sum0 += __shfl_xor_sync(0xffffffffu, sum0, 2);
        sum1 += __shfl_xor_sync(0xffffffffu, sum1, 1);
        sum1 += __shfl_xor_sync(0xffffffffu, sum1, 2);
        l_s[0] = l_s[0] * al0 + sum0;
        l_s[1] = l_s[1] * al1 + sum1;

#pragma unroll
        for (int j = 0; j < 8; j++) {
            o[j][0] *= al0; o[j][1] *= al0;
            o[j][2] *= al1; o[j][3] *= al1;
        }

#pragma unroll
        for (int kk = 0; kk < 4; kk++) {
            float* s0 = sc[2 * kk];
            float* s1 = sc[2 * kk + 1];
            uint32_t pa[4];
            pa[0] = pack_h2(s0[0], s0[1]);
            pa[1] = pack_h2(s0[2], s0[3]);
            pa[2] = pack_h2(s1[0], s1[1]);
            pa[3] = pack_h2(s1[2], s1[3]);
            const uint32_t rowk = (uint32_t)(kk * 16) * QROW_B;
#pragma unroll
            for (int j = 0; j < 4; j++) {
                uint32_t vv[4];
                ldsm4t(vv, sb + FV(s) + vOff + rowk + (uint32_t)(j * 32));
                MMA_F16(o[2 * j],     pa, vv[0], vv[1]);
                MMA_F16(o[2 * j + 1], pa, vv[2], vv[3]);
            }
        }
    }

    const int g  = lane >> 2;
    const int c2 = (lane & 3) * 2;
    const float inv0 = 1.f / l_s[0];
    const float inv1 = 1.f / l_s[1];
    const size_t row0 = rq + (size_t)(wid * 16 + g);
#pragma unroll
    for (int j = 0; j < 8; j++) {
        size_t i0 = (row0 * DM + h * DH + j * 8 + c2) >> 1;
        size_t i1 = ((row0 + 8) * DM + h * DH + j * 8 + c2) >> 1;
        O16[i0] = pack_h2(o[j][0] * inv0, o[j][1] * inv0);
        O16[i1] = pack_h2(o[j][2] * inv1, o[j][3] * inv1);
    }
}

// ---------------------------------------------------------------------------
// Launch
// ---------------------------------------------------------------------------
extern "C" void kernel_launch(void* const* d_in, const int* in_sizes, int n_in,
                              void* d_out, int out_size) {
    const float* x   = (const float*)d_in[0];
    const float* src = (const float*)d_in[1];
    const float* Wq  = (const float*)d_in[2];
    const float* Wk  = (const float*)d_in[3];
    const float* Wv  = (const float*)d_in[4];
    const float* Wo  = (const float*)d_in[5];
    float* out = (float*)d_out;

    void *x16, *s16, *q16, *k16, *v16, *o16;
    void *wq16, *wk16, *wv16, *wo16;
    cudaGetSymbolAddress(&x16, g_x16);
    cudaGetSymbolAddress(&s16, g_s16);
    cudaGetSymbolAddress(&q16, g_q16);
    cudaGetSymbolAddress(&k16, g_k16);
    cudaGetSymbolAddress(&v16, g_v16);
    cudaGetSymbolAddress(&o16, g_o16);
    cudaGetSymbolAddress(&wq16, g_wq16);
    cudaGetSymbolAddress(&wk16, g_wk16);
    cudaGetSymbolAddress(&wv16, g_wv16);
    cudaGetSymbolAddress(&wo16, g_wo16);

    cudaFuncSetAttribute(gemm_qkv8, cudaFuncAttributeMaxDynamicSharedMemorySize, GSMEM);
    cudaFuncSetAttribute(gemm_out8, cudaFuncAttributeMaxDynamicSharedMemorySize, GSMEM);
    cudaFuncSetAttribute(flash_v10, cudaFuncAttributeMaxDynamicSharedMemorySize, FSMEM);

    const float qs = 0.125f * 1.4426950408889634f;

    prep_all<<<(N4TOT + 255) / 256, 256>>>(
        (const float4*)x, (const float4*)src, (const float4*)Wq,
        (const float4*)Wk, (const float4*)Wv, (const float4*)Wo,
        (uint2*)x16, (uint2*)s16, (uint2*)wq16, (uint2*)wk16,
        (uint2*)wv16, (uint2*)wo16, qs);

    dim3 qkvgrid(DM / 128, M_TOT / 128, 3);    // (8, 32, 3)
    gemm_qkv8<<<qkvgrid, 256, GSMEM>>>(
        (const char*)x16, (const char*)s16,
        (const char*)wq16, (const char*)wk16, (const char*)wv16,
        (uint32_t*)q16, (uint32_t*)k16, (uint32_t*)v16);

    dim3 agrid(SEQ / 64, NH, BATCH);           // (32, 16, 2)
    flash_v10<<<agrid, 128, FSMEM>>>(
        (const char*)q16, (const char*)k16, (const char*)v16, (uint32_t*)o16);

    dim3 ggrid(DM / 128, M_TOT / 128);         // (8, 32)
    gemm_out8<<<ggrid, 256, GSMEM>>>(
        (const char*)o16, (const char*)wo16, out);
}